// round 3
// baseline (speedup 1.0000x reference)
#include <cuda_runtime.h>
#include <cuda_bf16.h>
#include <cstdint>

// Problem constants (RestGCNEqualHidden): N=50000, F=H=128, C=40, E=800000
#define MAXN 50000
#define MAXE 800000
#define FDIM 128
#define CDIM 40

// Scratch (device globals -- no allocation allowed)
__device__ int   g_is64;
__device__ int   g_src [MAXE];
__device__ int   g_dst [MAXE];
__device__ int   g_deg [MAXN];
__device__ float g_dinv[MAXN];
__device__ __align__(16) float g_g1  [(size_t)MAXN * FDIM];
__device__ __align__(16) float g_agg1[(size_t)MAXN * FDIM];
__device__ __align__(16) float g_g2  [(size_t)MAXN * CDIM];
__device__ __align__(16) float g_agg2[(size_t)MAXN * CDIM];

__device__ __forceinline__ void red_add_v4(float* addr, float4 v) {
    asm volatile("red.global.add.v4.f32 [%0], {%1,%2,%3,%4};"
                 :: "l"(addr), "f"(v.x), "f"(v.y), "f"(v.z), "f"(v.w)
                 : "memory");
}

// ---------------- dtype detect: int64 edges have zero high words ------------
__global__ void detect_kernel(const int* __restrict__ ei32) {
    if (threadIdx.x == 0 && blockIdx.x == 0) {
        int is64 = 1;
        for (int i = 1; i < 256; i += 2)
            if (ei32[i] != 0) { is64 = 0; break; }
        g_is64 = is64;
    }
}

// ---------------- convert edges to int32 + degree count ---------------------
__global__ void convert_kernel(const void* __restrict__ ei, int E) {
    int i = blockIdx.x * blockDim.x + threadIdx.x;
    if (i >= E) return;
    int s, d;
    if (g_is64) {
        const long long* p = (const long long*)ei;
        s = (int)p[i];
        d = (int)p[(size_t)E + i];
    } else {
        const int* p = (const int*)ei;
        s = p[i];
        d = p[E + i];
    }
    g_src[i] = s;
    g_dst[i] = d;
    atomicAdd(&g_deg[d], 1);
}

__global__ void dinv_kernel(int N) {
    int i = blockIdx.x * blockDim.x + threadIdx.x;
    if (i < N) g_dinv[i] = rsqrtf((float)g_deg[i] + 1.0f);  // +1 self loop
}

// ---------------- GEMM1: g1 = (x @ W1) * dinv ; agg1 = g1 (self loop) -------
// tile 64 rows x 128 cols, K=128 in one shot. 256 threads, each 8x4 outputs.
__global__ void gemm1_kernel(const float* __restrict__ x,
                             const float* __restrict__ W, int N) {
    extern __shared__ float sm[];
    float* sX = sm;               // 64 * 128
    float* sW = sm + 64 * 128;    // 128 * 128
    int tid  = threadIdx.x;
    int row0 = blockIdx.x * 64;

    const float4* W4 = (const float4*)W;
    float4* sW4 = (float4*)sW;
#pragma unroll
    for (int i = 0; i < 16; i++) sW4[tid + i * 256] = W4[tid + i * 256];

    const float4* X4 = (const float4*)x;
    float4* sX4 = (float4*)sX;
#pragma unroll
    for (int i = 0; i < 8; i++) {
        int f = tid + i * 256;           // [0, 2048)
        int r = f >> 5, c4 = f & 31;
        float4 v = make_float4(0.f, 0.f, 0.f, 0.f);
        if (row0 + r < N) v = X4[(size_t)(row0 + r) * 32 + c4];
        sX4[f] = v;
    }
    __syncthreads();

    int cg = tid & 31;   // 32 col-groups * 4 cols
    int rg = tid >> 5;   // 8 row-groups * 8 rows
    float acc[8][4] = {};
#pragma unroll 8
    for (int k = 0; k < 128; k++) {
        float4 wv = ((const float4*)(sW + k * 128))[cg];
        float xr[8];
#pragma unroll
        for (int i = 0; i < 8; i++) xr[i] = sX[(rg * 8 + i) * 128 + k];
#pragma unroll
        for (int i = 0; i < 8; i++) {
            acc[i][0] += xr[i] * wv.x;
            acc[i][1] += xr[i] * wv.y;
            acc[i][2] += xr[i] * wv.z;
            acc[i][3] += xr[i] * wv.w;
        }
    }
#pragma unroll
    for (int i = 0; i < 8; i++) {
        int r = row0 + rg * 8 + i;
        if (r < N) {
            float dv = g_dinv[r];
            float4 o = make_float4(acc[i][0] * dv, acc[i][1] * dv,
                                   acc[i][2] * dv, acc[i][3] * dv);
            ((float4*)g_g1)  [(size_t)r * 32 + cg] = o;
            ((float4*)g_agg1)[(size_t)r * 32 + cg] = o;
        }
    }
}

// ---------------- edge scatter layer 1: agg1[dst] += g1[src] ----------------
// one warp per edge, 32 lanes x float4 = 128 floats
__global__ void scatter1_kernel(int E) {
    int w = blockIdx.x * 8 + (threadIdx.x >> 5);
    int lane = threadIdx.x & 31;
    if (w >= E) return;
    int s = g_src[w];
    int d = g_dst[w];
    float4 v = ((const float4*)g_g1)[(size_t)s * 32 + lane];
    red_add_v4(&g_agg1[(size_t)d * FDIM + lane * 4], v);
}

// ---- fuse: x1c = relu(agg1*dinv + b1) + x  (written in place into agg1) ----
__global__ void fuse1_kernel(const float4* __restrict__ x,
                             const float* __restrict__ b1, int N) {
    int idx = blockIdx.x * blockDim.x + threadIdx.x;
    if (idx >= N * 32) return;
    int r = idx >> 5, c = idx & 31;
    float dv = g_dinv[r];
    float4 a  = ((float4*)g_agg1)[idx];
    float4 xv = x[idx];
    float4 b  = ((const float4*)b1)[c];
    float4 o;
    o.x = fmaxf(fmaf(a.x, dv, b.x), 0.f) + xv.x;
    o.y = fmaxf(fmaf(a.y, dv, b.y), 0.f) + xv.y;
    o.z = fmaxf(fmaf(a.z, dv, b.z), 0.f) + xv.z;
    o.w = fmaxf(fmaf(a.w, dv, b.w), 0.f) + xv.w;
    ((float4*)g_agg1)[idx] = o;
}

// ---------------- GEMM2: g2 = (x1c @ W2) * dinv ; agg2 = g2 ----------------
// tile 128 rows x 40 cols, 256 threads each 4x5 outputs. sX padded to 132.
__global__ void gemm2_kernel(const float* __restrict__ W, int N) {
    extern __shared__ float sm[];
    float* sX = sm;                 // 128 * 132
    float* sW = sm + 128 * 132;     // 128 * 40
    int tid  = threadIdx.x;
    int row0 = blockIdx.x * 128;

#pragma unroll
    for (int i = 0; i < 5; i++)
        ((float4*)sW)[tid + i * 256] = ((const float4*)W)[tid + i * 256];

#pragma unroll
    for (int i = 0; i < 16; i++) {
        int f = tid + i * 256;          // [0, 4096)
        int r = f >> 5, c4 = f & 31;
        float4 v = make_float4(0.f, 0.f, 0.f, 0.f);
        if (row0 + r < N) v = ((const float4*)g_agg1)[(size_t)(row0 + r) * 32 + c4];
        *((float4*)(sX + r * 132 + c4 * 4)) = v;
    }
    __syncthreads();

    int cg = tid & 7;    // 8 col-groups * 5 cols
    int rg = tid >> 3;   // 32 row-groups * 4 rows
    float acc[4][5] = {};
#pragma unroll 4
    for (int k = 0; k < 128; k++) {
        float wv[5];
#pragma unroll
        for (int j = 0; j < 5; j++) wv[j] = sW[k * 40 + cg * 5 + j];
#pragma unroll
        for (int i = 0; i < 4; i++) {
            float xv = sX[(rg * 4 + i) * 132 + k];
#pragma unroll
            for (int j = 0; j < 5; j++) acc[i][j] += xv * wv[j];
        }
    }
#pragma unroll
    for (int i = 0; i < 4; i++) {
        int r = row0 + rg * 4 + i;
        if (r < N) {
            float dv = g_dinv[r];
#pragma unroll
            for (int j = 0; j < 5; j++) {
                float o = acc[i][j] * dv;
                g_g2  [(size_t)r * 40 + cg * 5 + j] = o;
                g_agg2[(size_t)r * 40 + cg * 5 + j] = o;
            }
        }
    }
}

// ---------------- edge scatter layer 2: agg2[dst] += g2[src] ----------------
// thread handles one float4 chunk: 10 chunks per edge
__global__ void scatter2_kernel(int E) {
    int idx = blockIdx.x * blockDim.x + threadIdx.x;
    if (idx >= E * 10) return;
    int e = idx / 10, c = idx - e * 10;
    int s = g_src[e];
    int d = g_dst[e];
    float4 v = ((const float4*)g_g2)[(size_t)s * 10 + c];
    red_add_v4(&g_agg2[(size_t)d * CDIM + c * 4], v);
}

// ---------------- final: y = agg2 * dinv + b2 ----------------
__global__ void final_kernel(const float* __restrict__ b2,
                             float4* __restrict__ out, int N) {
    int idx = blockIdx.x * blockDim.x + threadIdx.x;
    if (idx >= N * 10) return;
    int r = idx / 10, c = idx - r * 10;
    float dv = g_dinv[r];
    float4 a = ((const float4*)g_agg2)[idx];
    float4 b = ((const float4*)b2)[c];
    float4 o;
    o.x = fmaf(a.x, dv, b.x);
    o.y = fmaf(a.y, dv, b.y);
    o.z = fmaf(a.z, dv, b.z);
    o.w = fmaf(a.w, dv, b.w);
    out[idx] = o;
}

extern "C" void kernel_launch(void* const* d_in, const int* in_sizes, int n_in,
                              void* d_out, int out_size) {
    const float* x  = (const float*)d_in[0];
    const void*  ei = (const void*)d_in[1];
    const float* W1 = (const float*)d_in[2];
    const float* b1 = (const float*)d_in[3];
    const float* W2 = (const float*)d_in[4];
    const float* b2 = (const float*)d_in[5];

    int N = in_sizes[0] / FDIM;     // 50000
    int E = in_sizes[1] / 2;        // 800000

    // zero degree counters
    void* degp = nullptr;
    cudaGetSymbolAddress(&degp, g_deg);
    cudaMemsetAsync(degp, 0, (size_t)N * sizeof(int));

    int smem1 = (64 * 128 + 128 * 128) * sizeof(float);      // 96 KB
    int smem2 = (128 * 132 + 128 * 40) * sizeof(float);      // ~86 KB
    cudaFuncSetAttribute(gemm1_kernel, cudaFuncAttributeMaxDynamicSharedMemorySize, smem1);
    cudaFuncSetAttribute(gemm2_kernel, cudaFuncAttributeMaxDynamicSharedMemorySize, smem2);

    detect_kernel<<<1, 32>>>((const int*)ei);
    convert_kernel<<<(E + 255) / 256, 256>>>(ei, E);
    dinv_kernel<<<(N + 255) / 256, 256>>>(N);

    gemm1_kernel<<<(N + 63) / 64, 256, smem1>>>(x, W1, N);
    scatter1_kernel<<<(E + 7) / 8, 256>>>(E);
    fuse1_kernel<<<(N * 32 + 255) / 256, 256>>>((const float4*)x, b1, N);

    gemm2_kernel<<<(N + 127) / 128, 256, smem2>>>(W2, N);
    scatter2_kernel<<<(E * 10 + 255) / 256, 256>>>(E);
    final_kernel<<<(N * 10 + 255) / 256, 256>>>(b2, (float4*)d_out, N);
}